// round 3
// baseline (speedup 1.0000x reference)
#include <cuda_runtime.h>
#include <math.h>

#define NN   50000
#define N2   (2 * NN)
#define NE_  800000
#define E2X  (2 * NE_)
#define NB   4096
#define NEX  8
#define EMBD 64
#define E2M  131072

// ---- device scratch (no allocations allowed) ----
__device__ __align__(16) float g_xw[N2 * 64];   // xs = dinv * (X@W)
__device__ __align__(16) float g_h[N2 * 64];    // hidden after conv1
__device__ __align__(16) float g_dinv[N2];
__device__ __align__(16) int   g_cnt_i[N2];
__device__ __align__(16) int   g_starts[N2 + 1];
__device__ __align__(16) int   g_cursor[N2];
__device__ __align__(16) int   g_csr[E2X];
__device__ __align__(16) float g_pool[NB * 64];
__device__ __align__(16) float g_cnt[2 * NB];
__device__ __align__(16) int   g_bins2[NB];
__device__ __align__(16) int   g_starts2[NB + 1];
__device__ __align__(16) int   g_cursor2[NB];
__device__ __align__(16) int   g_order[E2M];
__device__ float g_loss[1];

static __device__ __forceinline__ void red_add_v4(float4* p, float4 v) {
    asm volatile("red.global.add.v4.f32 [%0], {%1, %2, %3, %4};"
                 :: "l"(p), "f"(v.x), "f"(v.y), "f"(v.z), "f"(v.w)
                 : "memory");
}

// ---------------- histogram over BOTH scales' dst ----------------
__global__ void k_hist2(const int* __restrict__ dst0, const int* __restrict__ dst1, int E) {
    int e = blockIdx.x * blockDim.x + threadIdx.x;
    if (e < E)           atomicAdd(&g_cnt_i[dst0[e]], 1);
    else if (e < 2 * E)  atomicAdd(&g_cnt_i[dst1[e - E] + NN], 1);
}

// ---------------- loss-edge histogram ----------------
__global__ void k_hist(const int* __restrict__ key, int* __restrict__ bins, int n) {
    int e = blockIdx.x * blockDim.x + threadIdx.x;
    if (e < n) atomicAdd(&bins[key[e]], 1);
}

// ---------------- single-block exclusive scan ----------------
__global__ void k_scan(const int* __restrict__ cnt, int n,
                       int* __restrict__ starts, int* __restrict__ cursor,
                       float* __restrict__ dinv, int total) {
    __shared__ int ts[1024];
    int t = threadIdx.x;
    int CH = (n + 1023) >> 10;
    int beg = t * CH;
    int end = min(beg + CH, n);
    int s = 0;
    for (int i = beg; i < end; i++) s += cnt[i];
    ts[t] = s;
    __syncthreads();
    for (int o = 1; o < 1024; o <<= 1) {
        int u = (t >= o) ? ts[t - o] : 0;
        __syncthreads();
        ts[t] += u;
        __syncthreads();
    }
    int off = ts[t] - s;   // exclusive
    for (int i = beg; i < end; i++) {
        starts[i] = off;
        cursor[i] = off;
        if (dinv) dinv[i] = rsqrtf((float)cnt[i] + 1.0f);
        off += cnt[i];
    }
    if (t == 0) starts[n] = total;
}

// ---------------- CSR fill over both scales ----------------
__global__ void k_fill(const int* __restrict__ ei0, const int* __restrict__ ei1, int E) {
    int e = blockIdx.x * blockDim.x + threadIdx.x;
    int s, d;
    if (e < E)          { s = ei0[e];         d = ei0[E + e]; }
    else if (e < 2 * E) { s = ei1[e - E] + NN; d = ei1[E + e - E] + NN; }
    else return;
    int pos = atomicAdd(&g_cursor[d], 1);
    g_csr[pos] = s;
}

// ---------------- loss-edge bucket fill ----------------
__global__ void k_fill2(const int* __restrict__ srow, int E2) {
    int e = blockIdx.x * blockDim.x + threadIdx.x;
    if (e >= E2) return;
    int pos = atomicAdd(&g_cursor2[srow[e]], 1);
    g_order[pos] = e;
}

// ------- GEMM: g_xw = dinv * (X @ W).  PARTS threads per row, 16 cols each -------
template <int KOUT>
__global__ void k_gemm(const float* __restrict__ X0, const float* __restrict__ X1,
                       int splitN, const float* __restrict__ W, int n2) {
    constexpr int PARTS = KOUT / 16;
    __shared__ float Ws[64 * KOUT];
    for (int i = threadIdx.x; i < 64 * KOUT; i += blockDim.x) Ws[i] = W[i];
    __syncthreads();
    int idx = blockIdx.x * blockDim.x + threadIdx.x;
    int row = idx / PARTS;
    int part = idx - row * PARTS;
    if (row >= n2) return;
    const float4* xr = (const float4*)((row < splitN)
                       ? (X0 + (size_t)row * 64)
                       : (X1 + (size_t)(row - splitN) * 64));
    float acc[16];
#pragma unroll
    for (int c = 0; c < 16; c++) acc[c] = 0.0f;
#pragma unroll 4
    for (int kk = 0; kk < 16; kk++) {
        float4 xv = xr[kk];
#pragma unroll
        for (int j = 0; j < 4; j++) {
            float xk = (j == 0) ? xv.x : (j == 1) ? xv.y : (j == 2) ? xv.z : xv.w;
            const float4* wrow = (const float4*)(Ws + (kk * 4 + j) * KOUT + part * 16);
            float4 w0 = wrow[0], w1 = wrow[1], w2 = wrow[2], w3 = wrow[3];
            acc[0]  += xk * w0.x; acc[1]  += xk * w0.y; acc[2]  += xk * w0.z; acc[3]  += xk * w0.w;
            acc[4]  += xk * w1.x; acc[5]  += xk * w1.y; acc[6]  += xk * w1.z; acc[7]  += xk * w1.w;
            acc[8]  += xk * w2.x; acc[9]  += xk * w2.y; acc[10] += xk * w2.z; acc[11] += xk * w2.w;
            acc[12] += xk * w3.x; acc[13] += xk * w3.y; acc[14] += xk * w3.z; acc[15] += xk * w3.w;
        }
    }
    float di = g_dinv[row];
    float4* y4 = (float4*)(g_xw + (size_t)row * KOUT + part * 16);
#pragma unroll
    for (int j = 0; j < 4; j++)
        y4[j] = make_float4(di * acc[4 * j], di * acc[4 * j + 1],
                            di * acc[4 * j + 2], di * acc[4 * j + 3]);
}

// ------------- gather conv1: h = dinv_d*(sum_in xs + xs_d) + b1  (C=64) -------------
__global__ void k_gather1(const float* __restrict__ bias, int n2) {
    int idx = blockIdx.x * blockDim.x + threadIdx.x;
    int i = idx >> 4;
    int q = idx & 15;
    if (i >= n2) return;
    const float4* xs4 = (const float4*)g_xw;
    float4 acc = xs4[(size_t)i * 16 + q];     // self term
    int b0 = g_starts[i], b1 = g_starts[i + 1];
    int j = b0;
    for (; j + 1 < b1; j += 2) {
        int s0 = g_csr[j], s1 = g_csr[j + 1];
        float4 v0 = xs4[(size_t)s0 * 16 + q];
        float4 v1 = xs4[(size_t)s1 * 16 + q];
        acc.x += v0.x + v1.x; acc.y += v0.y + v1.y;
        acc.z += v0.z + v1.z; acc.w += v0.w + v1.w;
    }
    if (j < b1) {
        float4 v = xs4[(size_t)g_csr[j] * 16 + q];
        acc.x += v.x; acc.y += v.y; acc.z += v.z; acc.w += v.w;
    }
    float di = g_dinv[i];
    float4 bq = ((const float4*)bias)[q];
    ((float4*)g_h)[(size_t)i * 16 + q] =
        make_float4(di * acc.x + bq.x, di * acc.y + bq.y,
                    di * acc.z + bq.z, di * acc.w + bq.w);
}

// ------------- gather conv2 + fused mean-pool accumulate (C=32) -------------
__global__ void k_gather2(const float* __restrict__ bias, const int* __restrict__ bat0,
                          const int* __restrict__ bat1, int n2) {
    int idx = blockIdx.x * blockDim.x + threadIdx.x;
    int i = idx >> 3;
    int q = idx & 7;
    if (i >= n2) return;
    const float4* xs4 = (const float4*)g_xw;
    float4 acc = xs4[(size_t)i * 8 + q];
    int b0 = g_starts[i], b1 = g_starts[i + 1];
    int j = b0;
    for (; j + 1 < b1; j += 2) {
        int s0 = g_csr[j], s1 = g_csr[j + 1];
        float4 v0 = xs4[(size_t)s0 * 8 + q];
        float4 v1 = xs4[(size_t)s1 * 8 + q];
        acc.x += v0.x + v1.x; acc.y += v0.y + v1.y;
        acc.z += v0.z + v1.z; acc.w += v0.w + v1.w;
    }
    if (j < b1) {
        float4 v = xs4[(size_t)g_csr[j] * 8 + q];
        acc.x += v.x; acc.y += v.y; acc.z += v.z; acc.w += v.w;
    }
    float di = g_dinv[i];
    float4 bq = ((const float4*)bias)[q];
    float4 h2 = make_float4(di * acc.x + bq.x, di * acc.y + bq.y,
                            di * acc.z + bq.z, di * acc.w + bq.w);
    int scale = (i < NN) ? 0 : 1;
    int b = (i < NN) ? bat0[i] : bat1[i - NN];
    red_add_v4(((float4*)g_pool) + b * 16 + scale * 8 + q, h2);
}

// ---------------- per-graph node count, both scales ----------------
__global__ void k_cnt(const int* __restrict__ bat0, const int* __restrict__ bat1, int n2) {
    int i = blockIdx.x * blockDim.x + threadIdx.x;
    if (i >= n2) return;
    if (i < NN) atomicAdd(&g_cnt[bat0[i]], 1.0f);
    else        atomicAdd(&g_cnt[NB + bat1[i - NN]], 1.0f);
}

// ---------------- gate = softmax(concat(x0,x1) @ Wc + bc) ----------------
__global__ void k_gate(const float* __restrict__ Wc, const float* __restrict__ bc,
                       float* __restrict__ out, int B) {
    int b = blockIdx.x * blockDim.x + threadIdx.x;
    if (b >= B) return;
    float inv0 = 1.0f / fmaxf(g_cnt[b], 1.0f);
    float inv1 = 1.0f / fmaxf(g_cnt[NB + b], 1.0f);
    float logit[NEX];
#pragma unroll
    for (int e = 0; e < NEX; e++) logit[e] = bc[e];
    const float* pr = g_pool + b * 64;
    for (int k = 0; k < 64; k++) {
        float xv = pr[k] * (k < 32 ? inv0 : inv1);
#pragma unroll
        for (int e = 0; e < NEX; e++) logit[e] += xv * Wc[k * NEX + e];
    }
    float m = logit[0];
#pragma unroll
    for (int e = 1; e < NEX; e++) m = fmaxf(m, logit[e]);
    float ssum = 0.0f;
#pragma unroll
    for (int e = 0; e < NEX; e++) { logit[e] = expf(logit[e] - m); ssum += logit[e]; }
    float is = 1.0f / ssum;
#pragma unroll
    for (int e = 0; e < NEX; e++) out[b * NEX + e] = logit[e] * is;
}

// ---------- distortion loss, bucketed by source graph: 1 block per graph ----------
__global__ void k_loss(const float* __restrict__ emb, const float* __restrict__ gate,
                       const float* __restrict__ dis, const int* __restrict__ ei2, int E2) {
    __shared__ float sa[NEX * EMBD];       // emb[g] row (512 floats)
    __shared__ float warp_part[8];
    int g = blockIdx.x;
    int tid = threadIdx.x;
    for (int i = tid; i < NEX * EMBD; i += blockDim.x)
        sa[i] = emb[(long)g * (NEX * EMBD) + i];
    __syncthreads();

    int lane = tid & 31;
    int w = tid >> 5;
    int myex = lane & 7;
    int ex = lane >> 2;
    int ch = lane & 3;
    float gs = gate[g * NEX + myex];
    const float4* Ap = ((const float4*)sa) + ex * 16 + ch * 4;

    float part = 0.0f;
    int b0 = g_starts2[g], b1 = g_starts2[g + 1];
    for (int j = b0 + w; j < b1; j += 8) {
        int e = g_order[j];
        int d = ei2[E2 + e];
        const float4* Bp = (const float4*)(emb + (long)d * (NEX * EMBD)) + ex * 16 + ch * 4;
        float acc = 0.0f;
#pragma unroll
        for (int k = 0; k < 4; k++) {
            float4 a = Ap[k], b = Bp[k];
            float dx = a.x - b.x, dy = a.y - b.y, dz = a.z - b.z, dw = a.w - b.w;
            acc += dx * dx + dy * dy + dz * dz + dw * dw;
        }
        acc += __shfl_xor_sync(0xffffffffu, acc, 1);
        acc += __shfl_xor_sync(0xffffffffu, acc, 2);
        float de = __shfl_sync(0xffffffffu, acc, (lane & 7) * 4);
        float gp = gs * gate[d * NEX + myex];
        float m = gp;
#pragma unroll
        for (int o = 1; o < 8; o <<= 1) m = fmaxf(m, __shfl_xor_sync(0xffffffffu, m, o, 8));
        float wgt = expf(gp - m);
        float sw = wgt;
#pragma unroll
        for (int o = 1; o < 8; o <<= 1) sw += __shfl_xor_sync(0xffffffffu, sw, o, 8);
        float num = de * wgt;
#pragma unroll
        for (int o = 1; o < 8; o <<= 1) num += __shfl_xor_sync(0xffffffffu, num, o, 8);
        if (lane == 0) part += fabsf(num / sw / dis[e] - 1.0f);
    }
    if (lane == 0) warp_part[w] = part;
    __syncthreads();
    if (tid == 0) {
        float s = 0.0f;
#pragma unroll
        for (int k = 0; k < 8; k++) s += warp_part[k];
        atomicAdd(g_loss, s);
    }
}

__global__ void k_final(float* __restrict__ lossp, float invE2) {
    lossp[0] = g_loss[0] * invE2;
}

extern "C" void kernel_launch(void* const* d_in, const int* in_sizes, int n_in,
                              void* d_out, int out_size) {
    const float* x0   = (const float*)d_in[0];
    const float* x1   = (const float*)d_in[1];
    const float* W1   = (const float*)d_in[2];
    const float* b1   = (const float*)d_in[3];
    const float* W2   = (const float*)d_in[4];
    const float* b2   = (const float*)d_in[5];
    const float* Wc   = (const float*)d_in[6];
    const float* bc   = (const float*)d_in[7];
    const float* emb  = (const float*)d_in[8];
    const float* dis  = (const float*)d_in[9];
    const int*   ei0  = (const int*)d_in[10];
    const int*   ei1  = (const int*)d_in[11];
    const int*   bat0 = (const int*)d_in[12];
    const int*   bat1 = (const int*)d_in[13];
    const int*   ei2  = (const int*)d_in[14];

    int N  = in_sizes[0] / 64;
    int E  = in_sizes[10] / 2;
    int B  = in_sizes[8] / (NEX * EMBD);
    int E2 = in_sizes[14] / 2;
    int n2 = 2 * N;

    float* out = (float*)d_out;
    float* lossp = out + (out_size - 1);

    void *p_cnt_i, *p_starts, *p_cursor, *p_dinv, *p_pool, *p_cnt, *p_loss, *p_h;
    void *p_bins2, *p_starts2, *p_cursor2;
    cudaGetSymbolAddress(&p_cnt_i,  g_cnt_i);
    cudaGetSymbolAddress(&p_starts, g_starts);
    cudaGetSymbolAddress(&p_cursor, g_cursor);
    cudaGetSymbolAddress(&p_dinv,   g_dinv);
    cudaGetSymbolAddress(&p_pool,   g_pool);
    cudaGetSymbolAddress(&p_cnt,    g_cnt);
    cudaGetSymbolAddress(&p_loss,   g_loss);
    cudaGetSymbolAddress(&p_h,      g_h);
    cudaGetSymbolAddress(&p_bins2,  g_bins2);
    cudaGetSymbolAddress(&p_starts2, g_starts2);
    cudaGetSymbolAddress(&p_cursor2, g_cursor2);

    const int T = 256;
    cudaMemsetAsync(p_pool, 0, (size_t)NB * 64 * sizeof(float));
    cudaMemsetAsync(p_cnt,  0, (size_t)2 * NB * sizeof(float));
    cudaMemsetAsync(p_loss, 0, sizeof(float));
    cudaMemsetAsync(p_cnt_i, 0, (size_t)n2 * sizeof(int));
    cudaMemsetAsync(p_bins2, 0, (size_t)NB * sizeof(int));

    // loss-edge bucketing (independent of conv pipeline)
    k_hist<<<(E2 + T - 1) / T, T>>>(ei2, (int*)p_bins2, E2);
    k_scan<<<1, 1024>>>((const int*)p_bins2, B, (int*)p_starts2, (int*)p_cursor2,
                        (float*)0, E2);
    k_fill2<<<(E2 + T - 1) / T, T>>>(ei2, E2);

    // CSR build over both scales (+ dinv from degree)
    k_hist2<<<(2 * E + T - 1) / T, T>>>(ei0 + E, ei1 + E, E);
    k_scan<<<1, 1024>>>((const int*)p_cnt_i, n2, (int*)p_starts, (int*)p_cursor,
                        (float*)p_dinv, 2 * E);
    k_fill<<<(2 * E + T - 1) / T, T>>>(ei0, ei1, E);

    // conv1 (both scales fused)
    k_gemm<64><<<((long)n2 * 4 + T - 1) / T, T>>>(x0, x1, N, W1, n2);
    k_gather1<<<((long)n2 * 16 + T - 1) / T, T>>>(b1, n2);
    // conv2 + pool (both scales fused)
    k_gemm<32><<<((long)n2 * 2 + T - 1) / T, T>>>((const float*)p_h,
                                                  (const float*)p_h + (size_t)N * 64,
                                                  N, W2, n2);
    k_gather2<<<((long)n2 * 8 + T - 1) / T, T>>>(b2, bat0, bat1, n2);
    k_cnt<<<(n2 + T - 1) / T, T>>>(bat0, bat1, n2);

    // gating softmax -> d_out[0 .. B*8)
    k_gate<<<(B + T - 1) / T, T>>>(Wc, bc, out, B);

    // distortion loss (block per source graph) + finalize
    k_loss<<<B, 256>>>(emb, out, dis, ei2, E2);
    k_final<<<1, 1>>>(lossp, 1.0f / (float)E2);
}

// round 4
// speedup vs baseline: 1.5757x; 1.5757x over previous
#include <cuda_runtime.h>
#include <math.h>

#define NN   50000
#define N2   (2 * NN)
#define NE_  800000
#define E2X  (2 * NE_)
#define NB   4096
#define NEX  8
#define EMBD 64
#define E2M  131072
#define STILE 4096   // scan tile per block (256 threads * 16)

// ---- device scratch (no allocations allowed) ----
__device__ __align__(16) float g_xw[N2 * 64];   // xs = dinv * (X@W)
__device__ __align__(16) float g_h[N2 * 64];    // hidden after conv1
__device__ __align__(16) float g_dinv[N2];
__device__ __align__(16) int   g_cnt_i[N2];
__device__ __align__(16) int   g_starts[N2 + 1];
__device__ __align__(16) int   g_cursor[N2];
__device__ __align__(16) int   g_csr[E2X];
__device__ __align__(16) float g_pool[NB * 64];
__device__ __align__(16) float g_cnt[2 * NB];
__device__ __align__(16) int   g_bins2[NB];
__device__ __align__(16) int   g_starts2[NB + 1];
__device__ __align__(16) int   g_cursor2[NB];
__device__ __align__(16) int   g_order[E2M];
__device__ __align__(16) int   g_bsum[1024];
__device__ float g_loss[1];

static __device__ __forceinline__ void red_add_v4(float4* p, float4 v) {
    asm volatile("red.global.add.v4.f32 [%0], {%1, %2, %3, %4};"
                 :: "l"(p), "f"(v.x), "f"(v.y), "f"(v.z), "f"(v.w)
                 : "memory");
}

// ---------------- histogram over BOTH scales' dst ----------------
__global__ void k_hist2(const int* __restrict__ dst0, const int* __restrict__ dst1, int E) {
    int e = blockIdx.x * blockDim.x + threadIdx.x;
    if (e < E)           atomicAdd(&g_cnt_i[dst0[e]], 1);
    else if (e < 2 * E)  atomicAdd(&g_cnt_i[dst1[e - E] + NN], 1);
}

// ---------------- loss-edge histogram ----------------
__global__ void k_hist(const int* __restrict__ key, int* __restrict__ bins, int n) {
    int e = blockIdx.x * blockDim.x + threadIdx.x;
    if (e < n) atomicAdd(&bins[key[e]], 1);
}

// ================= 3-pass multi-block exclusive scan =================
// pass 1: per-block tile sums
__global__ void k_sc1(const int* __restrict__ cnt, int n) {
    int b = blockIdx.x, t = threadIdx.x;
    long base = (long)b * STILE + (long)t * 16;
    int s = 0;
    if (base + 16 <= n) {
        const int4* p = (const int4*)(cnt + base);
        int4 a = p[0], bb = p[1], c = p[2], d = p[3];
        s = a.x + a.y + a.z + a.w + bb.x + bb.y + bb.z + bb.w
          + c.x + c.y + c.z + c.w + d.x + d.y + d.z + d.w;
    } else {
        for (int k = 0; k < 16; k++) { long i = base + k; if (i < n) s += cnt[i]; }
    }
    __shared__ int sh[256];
    sh[t] = s;
    __syncthreads();
    for (int o = 128; o > 0; o >>= 1) {
        if (t < o) sh[t] += sh[t + o];
        __syncthreads();
    }
    if (t == 0) g_bsum[b] = sh[0];
}

// pass 2: exclusive scan of block sums (G <= 1024), single block
__global__ void k_sc2(int G) {
    __shared__ int sh[1024];
    int t = threadIdx.x;
    int v = (t < G) ? g_bsum[t] : 0;
    sh[t] = v;
    __syncthreads();
    for (int o = 1; o < 1024; o <<= 1) {
        int u = (t >= o) ? sh[t - o] : 0;
        __syncthreads();
        sh[t] += u;
        __syncthreads();
    }
    if (t < G) g_bsum[t] = sh[t] - v;   // exclusive
}

// pass 3: per-tile exclusive scan + write starts/cursor (+dinv)
__global__ void k_sc3(const int* __restrict__ cnt, int n,
                      int* __restrict__ starts, int* __restrict__ cursor,
                      float* __restrict__ dinv, int total) {
    int b = blockIdx.x, t = threadIdx.x;
    long base = (long)b * STILE + (long)t * 16;
    int c[16];
    bool full = (base + 16 <= n);
    if (full) {
        const int4* p = (const int4*)(cnt + base);
        int4 a0 = p[0], a1 = p[1], a2 = p[2], a3 = p[3];
        c[0] = a0.x; c[1] = a0.y; c[2] = a0.z; c[3] = a0.w;
        c[4] = a1.x; c[5] = a1.y; c[6] = a1.z; c[7] = a1.w;
        c[8] = a2.x; c[9] = a2.y; c[10] = a2.z; c[11] = a2.w;
        c[12] = a3.x; c[13] = a3.y; c[14] = a3.z; c[15] = a3.w;
    } else {
        for (int k = 0; k < 16; k++) { long i = base + k; c[k] = (i < n) ? cnt[i] : 0; }
    }
    int pref[16];
    int s = 0;
#pragma unroll
    for (int k = 0; k < 16; k++) { pref[k] = s; s += c[k]; }
    __shared__ int sh[256];
    sh[t] = s;
    __syncthreads();
    for (int o = 1; o < 256; o <<= 1) {
        int u = (t >= o) ? sh[t - o] : 0;
        __syncthreads();
        sh[t] += u;
        __syncthreads();
    }
    int off = g_bsum[b] + sh[t] - s;    // global exclusive offset of this thread's segment
    if (full) {
        int4 o4[4];
#pragma unroll
        for (int j = 0; j < 4; j++) {
            o4[j].x = off + pref[4 * j];     o4[j].y = off + pref[4 * j + 1];
            o4[j].z = off + pref[4 * j + 2]; o4[j].w = off + pref[4 * j + 3];
        }
        int4* ps = (int4*)(starts + base);
        int4* pc = (int4*)(cursor + base);
#pragma unroll
        for (int j = 0; j < 4; j++) { ps[j] = o4[j]; pc[j] = o4[j]; }
        if (dinv) {
            float4* pd = (float4*)(dinv + base);
#pragma unroll
            for (int j = 0; j < 4; j++)
                pd[j] = make_float4(rsqrtf((float)c[4 * j] + 1.0f),
                                    rsqrtf((float)c[4 * j + 1] + 1.0f),
                                    rsqrtf((float)c[4 * j + 2] + 1.0f),
                                    rsqrtf((float)c[4 * j + 3] + 1.0f));
        }
    } else {
        for (int k = 0; k < 16; k++) {
            long i = base + k;
            if (i < n) {
                int v = off + pref[k];
                starts[i] = v; cursor[i] = v;
                if (dinv) dinv[i] = rsqrtf((float)c[k] + 1.0f);
            }
        }
    }
    if (b == 0 && t == 0) starts[n] = total;
}

// ---------------- CSR fill over both scales ----------------
__global__ void k_fill(const int* __restrict__ ei0, const int* __restrict__ ei1, int E) {
    int e = blockIdx.x * blockDim.x + threadIdx.x;
    int s, d;
    if (e < E)          { s = ei0[e];          d = ei0[E + e]; }
    else if (e < 2 * E) { s = ei1[e - E] + NN; d = ei1[E + e - E] + NN; }
    else return;
    int pos = atomicAdd(&g_cursor[d], 1);
    g_csr[pos] = s;
}

// ---------------- loss-edge bucket fill ----------------
__global__ void k_fill2(const int* __restrict__ srow, int E2) {
    int e = blockIdx.x * blockDim.x + threadIdx.x;
    if (e >= E2) return;
    int pos = atomicAdd(&g_cursor2[srow[e]], 1);
    g_order[pos] = e;
}

// ------- GEMM: g_xw = dinv * (X @ W).  PARTS threads per row, 16 cols each -------
template <int KOUT>
__global__ void k_gemm(const float* __restrict__ X0, const float* __restrict__ X1,
                       int splitN, const float* __restrict__ W, int n2) {
    constexpr int PARTS = KOUT / 16;
    __shared__ float Ws[64 * KOUT];
    for (int i = threadIdx.x; i < 64 * KOUT; i += blockDim.x) Ws[i] = W[i];
    __syncthreads();
    int idx = blockIdx.x * blockDim.x + threadIdx.x;
    int row = idx / PARTS;
    int part = idx - row * PARTS;
    if (row >= n2) return;
    const float4* xr = (const float4*)((row < splitN)
                       ? (X0 + (size_t)row * 64)
                       : (X1 + (size_t)(row - splitN) * 64));
    float acc[16];
#pragma unroll
    for (int c = 0; c < 16; c++) acc[c] = 0.0f;
#pragma unroll 4
    for (int kk = 0; kk < 16; kk++) {
        float4 xv = xr[kk];
#pragma unroll
        for (int j = 0; j < 4; j++) {
            float xk = (j == 0) ? xv.x : (j == 1) ? xv.y : (j == 2) ? xv.z : xv.w;
            const float4* wrow = (const float4*)(Ws + (kk * 4 + j) * KOUT + part * 16);
            float4 w0 = wrow[0], w1 = wrow[1], w2 = wrow[2], w3 = wrow[3];
            acc[0]  += xk * w0.x; acc[1]  += xk * w0.y; acc[2]  += xk * w0.z; acc[3]  += xk * w0.w;
            acc[4]  += xk * w1.x; acc[5]  += xk * w1.y; acc[6]  += xk * w1.z; acc[7]  += xk * w1.w;
            acc[8]  += xk * w2.x; acc[9]  += xk * w2.y; acc[10] += xk * w2.z; acc[11] += xk * w2.w;
            acc[12] += xk * w3.x; acc[13] += xk * w3.y; acc[14] += xk * w3.z; acc[15] += xk * w3.w;
        }
    }
    float di = g_dinv[row];
    float4* y4 = (float4*)(g_xw + (size_t)row * KOUT + part * 16);
#pragma unroll
    for (int j = 0; j < 4; j++)
        y4[j] = make_float4(di * acc[4 * j], di * acc[4 * j + 1],
                            di * acc[4 * j + 2], di * acc[4 * j + 3]);
}

// ------------- gather conv1: h = dinv_d*(sum_in xs + xs_d) + b1  (C=64) -------------
__global__ void k_gather1(const float* __restrict__ bias, int n2) {
    int idx = blockIdx.x * blockDim.x + threadIdx.x;
    int i = idx >> 4;
    int q = idx & 15;
    if (i >= n2) return;
    const float4* xs4 = (const float4*)g_xw;
    float4 acc = xs4[(size_t)i * 16 + q];     // self term
    int b0 = g_starts[i], b1 = g_starts[i + 1];
    int j = b0;
    for (; j + 1 < b1; j += 2) {
        int s0 = g_csr[j], s1 = g_csr[j + 1];
        float4 v0 = xs4[(size_t)s0 * 16 + q];
        float4 v1 = xs4[(size_t)s1 * 16 + q];
        acc.x += v0.x + v1.x; acc.y += v0.y + v1.y;
        acc.z += v0.z + v1.z; acc.w += v0.w + v1.w;
    }
    if (j < b1) {
        float4 v = xs4[(size_t)g_csr[j] * 16 + q];
        acc.x += v.x; acc.y += v.y; acc.z += v.z; acc.w += v.w;
    }
    float di = g_dinv[i];
    float4 bq = ((const float4*)bias)[q];
    ((float4*)g_h)[(size_t)i * 16 + q] =
        make_float4(di * acc.x + bq.x, di * acc.y + bq.y,
                    di * acc.z + bq.z, di * acc.w + bq.w);
}

// ------------- gather conv2 + fused mean-pool accumulate (C=32) -------------
__global__ void k_gather2(const float* __restrict__ bias, const int* __restrict__ bat0,
                          const int* __restrict__ bat1, int n2) {
    int idx = blockIdx.x * blockDim.x + threadIdx.x;
    int i = idx >> 3;
    int q = idx & 7;
    if (i >= n2) return;
    const float4* xs4 = (const float4*)g_xw;
    float4 acc = xs4[(size_t)i * 8 + q];
    int b0 = g_starts[i], b1 = g_starts[i + 1];
    int j = b0;
    for (; j + 1 < b1; j += 2) {
        int s0 = g_csr[j], s1 = g_csr[j + 1];
        float4 v0 = xs4[(size_t)s0 * 8 + q];
        float4 v1 = xs4[(size_t)s1 * 8 + q];
        acc.x += v0.x + v1.x; acc.y += v0.y + v1.y;
        acc.z += v0.z + v1.z; acc.w += v0.w + v1.w;
    }
    if (j < b1) {
        float4 v = xs4[(size_t)g_csr[j] * 8 + q];
        acc.x += v.x; acc.y += v.y; acc.z += v.z; acc.w += v.w;
    }
    float di = g_dinv[i];
    float4 bq = ((const float4*)bias)[q];
    float4 h2 = make_float4(di * acc.x + bq.x, di * acc.y + bq.y,
                            di * acc.z + bq.z, di * acc.w + bq.w);
    int scale = (i < NN) ? 0 : 1;
    int b = (i < NN) ? bat0[i] : bat1[i - NN];
    red_add_v4(((float4*)g_pool) + b * 16 + scale * 8 + q, h2);
}

// ---------------- per-graph node count, both scales ----------------
__global__ void k_cnt(const int* __restrict__ bat0, const int* __restrict__ bat1, int n2) {
    int i = blockIdx.x * blockDim.x + threadIdx.x;
    if (i >= n2) return;
    if (i < NN) atomicAdd(&g_cnt[bat0[i]], 1.0f);
    else        atomicAdd(&g_cnt[NB + bat1[i - NN]], 1.0f);
}

// ---------------- gate = softmax(concat(x0,x1) @ Wc + bc) ----------------
__global__ void k_gate(const float* __restrict__ Wc, const float* __restrict__ bc,
                       float* __restrict__ out, int B) {
    int b = blockIdx.x * blockDim.x + threadIdx.x;
    if (b >= B) return;
    float inv0 = 1.0f / fmaxf(g_cnt[b], 1.0f);
    float inv1 = 1.0f / fmaxf(g_cnt[NB + b], 1.0f);
    float logit[NEX];
#pragma unroll
    for (int e = 0; e < NEX; e++) logit[e] = bc[e];
    const float* pr = g_pool + b * 64;
    for (int k = 0; k < 64; k++) {
        float xv = pr[k] * (k < 32 ? inv0 : inv1);
#pragma unroll
        for (int e = 0; e < NEX; e++) logit[e] += xv * Wc[k * NEX + e];
    }
    float m = logit[0];
#pragma unroll
    for (int e = 1; e < NEX; e++) m = fmaxf(m, logit[e]);
    float ssum = 0.0f;
#pragma unroll
    for (int e = 0; e < NEX; e++) { logit[e] = expf(logit[e] - m); ssum += logit[e]; }
    float is = 1.0f / ssum;
#pragma unroll
    for (int e = 0; e < NEX; e++) out[b * NEX + e] = logit[e] * is;
}

// ---------- distortion loss, bucketed by source graph: 1 block per graph ----------
__global__ void k_loss(const float* __restrict__ emb, const float* __restrict__ gate,
                       const float* __restrict__ dis, const int* __restrict__ ei2, int E2) {
    __shared__ float sa[NEX * EMBD];       // emb[g] row (512 floats)
    __shared__ float warp_part[8];
    int g = blockIdx.x;
    int tid = threadIdx.x;
    for (int i = tid; i < NEX * EMBD; i += blockDim.x)
        sa[i] = emb[(long)g * (NEX * EMBD) + i];
    __syncthreads();

    int lane = tid & 31;
    int w = tid >> 5;
    int myex = lane & 7;
    int ex = lane >> 2;
    int ch = lane & 3;
    float gs = gate[g * NEX + myex];
    const float4* Ap = ((const float4*)sa) + ex * 16 + ch * 4;

    float part = 0.0f;
    int b0 = g_starts2[g], b1 = g_starts2[g + 1];
    for (int j = b0 + w; j < b1; j += 8) {
        int e = g_order[j];
        int d = ei2[E2 + e];
        const float4* Bp = (const float4*)(emb + (long)d * (NEX * EMBD)) + ex * 16 + ch * 4;
        float acc = 0.0f;
#pragma unroll
        for (int k = 0; k < 4; k++) {
            float4 a = Ap[k], b = Bp[k];
            float dx = a.x - b.x, dy = a.y - b.y, dz = a.z - b.z, dw = a.w - b.w;
            acc += dx * dx + dy * dy + dz * dz + dw * dw;
        }
        acc += __shfl_xor_sync(0xffffffffu, acc, 1);
        acc += __shfl_xor_sync(0xffffffffu, acc, 2);
        float de = __shfl_sync(0xffffffffu, acc, (lane & 7) * 4);
        float gp = gs * gate[d * NEX + myex];
        float m = gp;
#pragma unroll
        for (int o = 1; o < 8; o <<= 1) m = fmaxf(m, __shfl_xor_sync(0xffffffffu, m, o, 8));
        float wgt = expf(gp - m);
        float sw = wgt;
#pragma unroll
        for (int o = 1; o < 8; o <<= 1) sw += __shfl_xor_sync(0xffffffffu, sw, o, 8);
        float num = de * wgt;
#pragma unroll
        for (int o = 1; o < 8; o <<= 1) num += __shfl_xor_sync(0xffffffffu, num, o, 8);
        if (lane == 0) part += fabsf(num / sw / dis[e] - 1.0f);
    }
    if (lane == 0) warp_part[w] = part;
    __syncthreads();
    if (tid == 0) {
        float s = 0.0f;
#pragma unroll
        for (int k = 0; k < 8; k++) s += warp_part[k];
        atomicAdd(g_loss, s);
    }
}

__global__ void k_final(float* __restrict__ lossp, float invE2) {
    lossp[0] = g_loss[0] * invE2;
}

extern "C" void kernel_launch(void* const* d_in, const int* in_sizes, int n_in,
                              void* d_out, int out_size) {
    const float* x0   = (const float*)d_in[0];
    const float* x1   = (const float*)d_in[1];
    const float* W1   = (const float*)d_in[2];
    const float* b1   = (const float*)d_in[3];
    const float* W2   = (const float*)d_in[4];
    const float* b2   = (const float*)d_in[5];
    const float* Wc   = (const float*)d_in[6];
    const float* bc   = (const float*)d_in[7];
    const float* emb  = (const float*)d_in[8];
    const float* dis  = (const float*)d_in[9];
    const int*   ei0  = (const int*)d_in[10];
    const int*   ei1  = (const int*)d_in[11];
    const int*   bat0 = (const int*)d_in[12];
    const int*   bat1 = (const int*)d_in[13];
    const int*   ei2  = (const int*)d_in[14];

    int N  = in_sizes[0] / 64;
    int E  = in_sizes[10] / 2;
    int B  = in_sizes[8] / (NEX * EMBD);
    int E2 = in_sizes[14] / 2;
    int n2 = 2 * N;

    float* out = (float*)d_out;
    float* lossp = out + (out_size - 1);

    void *p_cnt_i, *p_starts, *p_cursor, *p_dinv, *p_pool, *p_cnt, *p_loss;
    void *p_bins2, *p_starts2, *p_cursor2, *p_h;
    cudaGetSymbolAddress(&p_cnt_i,  g_cnt_i);
    cudaGetSymbolAddress(&p_starts, g_starts);
    cudaGetSymbolAddress(&p_cursor, g_cursor);
    cudaGetSymbolAddress(&p_dinv,   g_dinv);
    cudaGetSymbolAddress(&p_pool,   g_pool);
    cudaGetSymbolAddress(&p_cnt,    g_cnt);
    cudaGetSymbolAddress(&p_loss,   g_loss);
    cudaGetSymbolAddress(&p_h,      g_h);
    cudaGetSymbolAddress(&p_bins2,  g_bins2);
    cudaGetSymbolAddress(&p_starts2, g_starts2);
    cudaGetSymbolAddress(&p_cursor2, g_cursor2);

    const int T = 256;
    cudaMemsetAsync(p_pool, 0, (size_t)NB * 64 * sizeof(float));
    cudaMemsetAsync(p_cnt,  0, (size_t)2 * NB * sizeof(float));
    cudaMemsetAsync(p_loss, 0, sizeof(float));
    cudaMemsetAsync(p_cnt_i, 0, (size_t)n2 * sizeof(int));
    cudaMemsetAsync(p_bins2, 0, (size_t)NB * sizeof(int));

    // loss-edge bucketing (independent of conv pipeline)
    int G2 = (B + STILE - 1) / STILE;
    k_hist<<<(E2 + T - 1) / T, T>>>(ei2, (int*)p_bins2, E2);
    k_sc1<<<G2, 256>>>((const int*)p_bins2, B);
    k_sc2<<<1, 1024>>>(G2);
    k_sc3<<<G2, 256>>>((const int*)p_bins2, B, (int*)p_starts2, (int*)p_cursor2,
                       (float*)0, E2);
    k_fill2<<<(E2 + T - 1) / T, T>>>(ei2, E2);

    // CSR build over both scales (+ dinv from degree)
    int G = (n2 + STILE - 1) / STILE;
    k_hist2<<<(2 * E + T - 1) / T, T>>>(ei0 + E, ei1 + E, E);
    k_sc1<<<G, 256>>>((const int*)p_cnt_i, n2);
    k_sc2<<<1, 1024>>>(G);
    k_sc3<<<G, 256>>>((const int*)p_cnt_i, n2, (int*)p_starts, (int*)p_cursor,
                      (float*)p_dinv, 2 * E);
    k_fill<<<(2 * E + T - 1) / T, T>>>(ei0, ei1, E);

    // conv1 (both scales fused)
    k_gemm<64><<<((long)n2 * 4 + T - 1) / T, T>>>(x0, x1, N, W1, n2);
    k_gather1<<<((long)n2 * 16 + T - 1) / T, T>>>(b1, n2);
    // conv2 + pool (both scales fused)
    k_gemm<32><<<((long)n2 * 2 + T - 1) / T, T>>>((const float*)p_h,
                                                  (const float*)p_h + (size_t)N * 64,
                                                  N, W2, n2);
    k_gather2<<<((long)n2 * 8 + T - 1) / T, T>>>(b2, bat0, bat1, n2);
    k_cnt<<<(n2 + T - 1) / T, T>>>(bat0, bat1, n2);

    // gating softmax -> d_out[0 .. B*8)
    k_gate<<<(B + T - 1) / T, T>>>(Wc, bc, out, B);

    // distortion loss (block per source graph) + finalize
    k_loss<<<B, 256>>>(emb, out, dis, ei2, E2);
    k_final<<<1, 1>>>(lossp, 1.0f / (float)E2);
}

// round 5
// speedup vs baseline: 1.6663x; 1.0575x over previous
#include <cuda_runtime.h>
#include <math.h>

#define NN   50000
#define N2   (2 * NN)
#define NE_  800000
#define E2X  (2 * NE_)
#define NB   4096
#define NEX  8
#define EMBD 64
#define E2M  131072
#define STILE 4096   // scan tile per block (256 threads * 16)

// ---- device scratch (no allocations allowed) ----
__device__ __align__(16) float g_xw[N2 * 64];   // xs = dinv * (X@W)
__device__ __align__(16) float g_h[N2 * 64];    // hidden after conv1
__device__ __align__(16) float g_dinv[N2];
__device__ __align__(16) int   g_cnt_i[N2];
__device__ __align__(16) int   g_starts[N2 + 1];
__device__ __align__(16) int   g_cursor[N2];
__device__ __align__(16) int   g_csr[E2X];
__device__ __align__(16) float g_pool[NB * 64];
__device__ __align__(16) float g_cnt[2 * NB];
__device__ __align__(16) int   g_bins2[NB];
__device__ __align__(16) int   g_starts2[NB + 1];
__device__ __align__(16) int   g_cursor2[NB];
__device__ __align__(16) int   g_order[E2M];
__device__ __align__(16) int   g_bsum[1024];
__device__ __align__(16) int   g_bsum2[1024];
__device__ float g_loss[1];

static __device__ __forceinline__ void red_add_v4(float4* p, float4 v) {
    asm volatile("red.global.add.v4.f32 [%0], {%1, %2, %3, %4};"
                 :: "l"(p), "f"(v.x), "f"(v.y), "f"(v.z), "f"(v.w)
                 : "memory");
}

// ---------------- histogram over BOTH scales' dst ----------------
__global__ void k_hist2(const int* __restrict__ dst0, const int* __restrict__ dst1, int E) {
    int e = blockIdx.x * blockDim.x + threadIdx.x;
    if (e < E)           atomicAdd(&g_cnt_i[dst0[e]], 1);
    else if (e < 2 * E)  atomicAdd(&g_cnt_i[dst1[e - E] + NN], 1);
}

// ---------------- loss-edge histogram ----------------
__global__ void k_hist(const int* __restrict__ key, int* __restrict__ bins, int n) {
    int e = blockIdx.x * blockDim.x + threadIdx.x;
    if (e < n) atomicAdd(&bins[key[e]], 1);
}

// ================= 3-pass multi-block exclusive scan =================
__global__ void k_sc1(const int* __restrict__ cnt, int n, int* __restrict__ bsum) {
    int b = blockIdx.x, t = threadIdx.x;
    long base = (long)b * STILE + (long)t * 16;
    int s = 0;
    if (base + 16 <= n) {
        const int4* p = (const int4*)(cnt + base);
        int4 a = p[0], bb = p[1], c = p[2], d = p[3];
        s = a.x + a.y + a.z + a.w + bb.x + bb.y + bb.z + bb.w
          + c.x + c.y + c.z + c.w + d.x + d.y + d.z + d.w;
    } else {
        for (int k = 0; k < 16; k++) { long i = base + k; if (i < n) s += cnt[i]; }
    }
    __shared__ int sh[256];
    sh[t] = s;
    __syncthreads();
    for (int o = 128; o > 0; o >>= 1) {
        if (t < o) sh[t] += sh[t + o];
        __syncthreads();
    }
    if (t == 0) bsum[b] = sh[0];
}

__global__ void k_sc2(int G, int* __restrict__ bsum) {
    __shared__ int sh[1024];
    int t = threadIdx.x;
    int v = (t < G) ? bsum[t] : 0;
    sh[t] = v;
    __syncthreads();
    for (int o = 1; o < 1024; o <<= 1) {
        int u = (t >= o) ? sh[t - o] : 0;
        __syncthreads();
        sh[t] += u;
        __syncthreads();
    }
    if (t < G) bsum[t] = sh[t] - v;   // exclusive
}

__global__ void k_sc3(const int* __restrict__ cnt, int n,
                      int* __restrict__ starts, int* __restrict__ cursor,
                      float* __restrict__ dinv, int total, const int* __restrict__ bsum) {
    int b = blockIdx.x, t = threadIdx.x;
    long base = (long)b * STILE + (long)t * 16;
    int c[16];
    bool full = (base + 16 <= n);
    if (full) {
        const int4* p = (const int4*)(cnt + base);
        int4 a0 = p[0], a1 = p[1], a2 = p[2], a3 = p[3];
        c[0] = a0.x; c[1] = a0.y; c[2] = a0.z; c[3] = a0.w;
        c[4] = a1.x; c[5] = a1.y; c[6] = a1.z; c[7] = a1.w;
        c[8] = a2.x; c[9] = a2.y; c[10] = a2.z; c[11] = a2.w;
        c[12] = a3.x; c[13] = a3.y; c[14] = a3.z; c[15] = a3.w;
    } else {
        for (int k = 0; k < 16; k++) { long i = base + k; c[k] = (i < n) ? cnt[i] : 0; }
    }
    int pref[16];
    int s = 0;
#pragma unroll
    for (int k = 0; k < 16; k++) { pref[k] = s; s += c[k]; }
    __shared__ int sh[256];
    sh[t] = s;
    __syncthreads();
    for (int o = 1; o < 256; o <<= 1) {
        int u = (t >= o) ? sh[t - o] : 0;
        __syncthreads();
        sh[t] += u;
        __syncthreads();
    }
    int off = bsum[b] + sh[t] - s;
    if (full) {
        int4 o4[4];
#pragma unroll
        for (int j = 0; j < 4; j++) {
            o4[j].x = off + pref[4 * j];     o4[j].y = off + pref[4 * j + 1];
            o4[j].z = off + pref[4 * j + 2]; o4[j].w = off + pref[4 * j + 3];
        }
        int4* ps = (int4*)(starts + base);
        int4* pc = (int4*)(cursor + base);
#pragma unroll
        for (int j = 0; j < 4; j++) { ps[j] = o4[j]; pc[j] = o4[j]; }
        if (dinv) {
            float4* pd = (float4*)(dinv + base);
#pragma unroll
            for (int j = 0; j < 4; j++)
                pd[j] = make_float4(rsqrtf((float)c[4 * j] + 1.0f),
                                    rsqrtf((float)c[4 * j + 1] + 1.0f),
                                    rsqrtf((float)c[4 * j + 2] + 1.0f),
                                    rsqrtf((float)c[4 * j + 3] + 1.0f));
        }
    } else {
        for (int k = 0; k < 16; k++) {
            long i = base + k;
            if (i < n) {
                int v = off + pref[k];
                starts[i] = v; cursor[i] = v;
                if (dinv) dinv[i] = rsqrtf((float)c[k] + 1.0f);
            }
        }
    }
    if (b == 0 && t == 0) starts[n] = total;
}

// ---------------- CSR fill over both scales ----------------
__global__ void k_fill(const int* __restrict__ ei0, const int* __restrict__ ei1, int E) {
    int e = blockIdx.x * blockDim.x + threadIdx.x;
    int s, d;
    if (e < E)          { s = ei0[e];          d = ei0[E + e]; }
    else if (e < 2 * E) { s = ei1[e - E] + NN; d = ei1[E + e - E] + NN; }
    else return;
    int pos = atomicAdd(&g_cursor[d], 1);
    g_csr[pos] = s;
}

// ---------------- loss-edge bucket fill ----------------
__global__ void k_fill2(const int* __restrict__ srow, int E2) {
    int e = blockIdx.x * blockDim.x + threadIdx.x;
    if (e >= E2) return;
    int pos = atomicAdd(&g_cursor2[srow[e]], 1);
    g_order[pos] = e;
}

// ------- GEMM: g_xw = dinv * (X @ W).  PARTS threads per row, 16 cols each -------
template <int KOUT>
__global__ void k_gemm(const float* __restrict__ X0, const float* __restrict__ X1,
                       int splitN, const float* __restrict__ W, int n2) {
    constexpr int PARTS = KOUT / 16;
    __shared__ float Ws[64 * KOUT];
    for (int i = threadIdx.x; i < 64 * KOUT; i += blockDim.x) Ws[i] = W[i];
    __syncthreads();
    int idx = blockIdx.x * blockDim.x + threadIdx.x;
    int row = idx / PARTS;
    int part = idx - row * PARTS;
    if (row >= n2) return;
    const float4* xr = (const float4*)((row < splitN)
                       ? (X0 + (size_t)row * 64)
                       : (X1 + (size_t)(row - splitN) * 64));
    float acc[16];
#pragma unroll
    for (int c = 0; c < 16; c++) acc[c] = 0.0f;
#pragma unroll 4
    for (int kk = 0; kk < 16; kk++) {
        float4 xv = xr[kk];
#pragma unroll
        for (int j = 0; j < 4; j++) {
            float xk = (j == 0) ? xv.x : (j == 1) ? xv.y : (j == 2) ? xv.z : xv.w;
            const float4* wrow = (const float4*)(Ws + (kk * 4 + j) * KOUT + part * 16);
            float4 w0 = wrow[0], w1 = wrow[1], w2 = wrow[2], w3 = wrow[3];
            acc[0]  += xk * w0.x; acc[1]  += xk * w0.y; acc[2]  += xk * w0.z; acc[3]  += xk * w0.w;
            acc[4]  += xk * w1.x; acc[5]  += xk * w1.y; acc[6]  += xk * w1.z; acc[7]  += xk * w1.w;
            acc[8]  += xk * w2.x; acc[9]  += xk * w2.y; acc[10] += xk * w2.z; acc[11] += xk * w2.w;
            acc[12] += xk * w3.x; acc[13] += xk * w3.y; acc[14] += xk * w3.z; acc[15] += xk * w3.w;
        }
    }
    float di = g_dinv[row];
    float4* y4 = (float4*)(g_xw + (size_t)row * KOUT + part * 16);
#pragma unroll
    for (int j = 0; j < 4; j++)
        y4[j] = make_float4(di * acc[4 * j], di * acc[4 * j + 1],
                            di * acc[4 * j + 2], di * acc[4 * j + 3]);
}

// ------------- gather conv1: h = dinv_d*(sum_in xs + xs_d) + b1  (C=64) -------------
__global__ void k_gather1(const float* __restrict__ bias, int n2) {
    int idx = blockIdx.x * blockDim.x + threadIdx.x;
    int i = idx >> 4;
    int q = idx & 15;
    if (i >= n2) return;
    const float4* xs4 = (const float4*)g_xw;
    float4 acc = xs4[(size_t)i * 16 + q];     // self term
    int b0 = g_starts[i], b1 = g_starts[i + 1];
    int j = b0;
    for (; j + 1 < b1; j += 2) {
        int s0 = g_csr[j], s1 = g_csr[j + 1];
        float4 v0 = xs4[(size_t)s0 * 16 + q];
        float4 v1 = xs4[(size_t)s1 * 16 + q];
        acc.x += v0.x + v1.x; acc.y += v0.y + v1.y;
        acc.z += v0.z + v1.z; acc.w += v0.w + v1.w;
    }
    if (j < b1) {
        float4 v = xs4[(size_t)g_csr[j] * 16 + q];
        acc.x += v.x; acc.y += v.y; acc.z += v.z; acc.w += v.w;
    }
    float di = g_dinv[i];
    float4 bq = ((const float4*)bias)[q];
    ((float4*)g_h)[(size_t)i * 16 + q] =
        make_float4(di * acc.x + bq.x, di * acc.y + bq.y,
                    di * acc.z + bq.z, di * acc.w + bq.w);
}

// ------------- gather conv2 + fused mean-pool accumulate (C=32) -------------
__global__ void k_gather2(const float* __restrict__ bias, const int* __restrict__ bat0,
                          const int* __restrict__ bat1, int n2) {
    int idx = blockIdx.x * blockDim.x + threadIdx.x;
    int i = idx >> 3;
    int q = idx & 7;
    if (i >= n2) return;
    const float4* xs4 = (const float4*)g_xw;
    float4 acc = xs4[(size_t)i * 8 + q];
    int b0 = g_starts[i], b1 = g_starts[i + 1];
    int j = b0;
    for (; j + 1 < b1; j += 2) {
        int s0 = g_csr[j], s1 = g_csr[j + 1];
        float4 v0 = xs4[(size_t)s0 * 8 + q];
        float4 v1 = xs4[(size_t)s1 * 8 + q];
        acc.x += v0.x + v1.x; acc.y += v0.y + v1.y;
        acc.z += v0.z + v1.z; acc.w += v0.w + v1.w;
    }
    if (j < b1) {
        float4 v = xs4[(size_t)g_csr[j] * 8 + q];
        acc.x += v.x; acc.y += v.y; acc.z += v.z; acc.w += v.w;
    }
    float di = g_dinv[i];
    float4 bq = ((const float4*)bias)[q];
    float4 h2 = make_float4(di * acc.x + bq.x, di * acc.y + bq.y,
                            di * acc.z + bq.z, di * acc.w + bq.w);
    int scale = (i < NN) ? 0 : 1;
    int b = (i < NN) ? bat0[i] : bat1[i - NN];
    red_add_v4(((float4*)g_pool) + b * 16 + scale * 8 + q, h2);
}

// ---------------- per-graph node count, both scales ----------------
__global__ void k_cnt(const int* __restrict__ bat0, const int* __restrict__ bat1, int n2) {
    int i = blockIdx.x * blockDim.x + threadIdx.x;
    if (i >= n2) return;
    if (i < NN) atomicAdd(&g_cnt[bat0[i]], 1.0f);
    else        atomicAdd(&g_cnt[NB + bat1[i - NN]], 1.0f);
}

// ---------------- gate = softmax(concat(x0,x1) @ Wc + bc) ----------------
__global__ void k_gate(const float* __restrict__ Wc, const float* __restrict__ bc,
                       float* __restrict__ out, int B) {
    int b = blockIdx.x * blockDim.x + threadIdx.x;
    if (b >= B) return;
    float inv0 = 1.0f / fmaxf(g_cnt[b], 1.0f);
    float inv1 = 1.0f / fmaxf(g_cnt[NB + b], 1.0f);
    float logit[NEX];
#pragma unroll
    for (int e = 0; e < NEX; e++) logit[e] = bc[e];
    const float* pr = g_pool + b * 64;
    for (int k = 0; k < 64; k++) {
        float xv = pr[k] * (k < 32 ? inv0 : inv1);
#pragma unroll
        for (int e = 0; e < NEX; e++) logit[e] += xv * Wc[k * NEX + e];
    }
    float m = logit[0];
#pragma unroll
    for (int e = 1; e < NEX; e++) m = fmaxf(m, logit[e]);
    float ssum = 0.0f;
#pragma unroll
    for (int e = 0; e < NEX; e++) { logit[e] = expf(logit[e] - m); ssum += logit[e]; }
    float is = 1.0f / ssum;
#pragma unroll
    for (int e = 0; e < NEX; e++) out[b * NEX + e] = logit[e] * is;
}

// ---------- distortion loss, bucketed by source graph: 1 block per graph ----------
__global__ void k_loss(const float* __restrict__ emb, const float* __restrict__ gate,
                       const float* __restrict__ dis, const int* __restrict__ ei2, int E2) {
    __shared__ float sa[NEX * EMBD];       // emb[g] row (512 floats)
    __shared__ float warp_part[8];
    int g = blockIdx.x;
    int tid = threadIdx.x;
    for (int i = tid; i < NEX * EMBD; i += blockDim.x)
        sa[i] = emb[(long)g * (NEX * EMBD) + i];
    __syncthreads();

    int lane = tid & 31;
    int w = tid >> 5;
    int myex = lane & 7;
    int ex = lane >> 2;
    int ch = lane & 3;
    float gs = gate[g * NEX + myex];
    const float4* Ap = ((const float4*)sa) + ex * 16 + ch * 4;

    float part = 0.0f;
    int b0 = g_starts2[g], b1 = g_starts2[g + 1];
    for (int j = b0 + w; j < b1; j += 8) {
        int e = g_order[j];
        int d = ei2[E2 + e];
        const float4* Bp = (const float4*)(emb + (long)d * (NEX * EMBD)) + ex * 16 + ch * 4;
        float acc = 0.0f;
#pragma unroll
        for (int k = 0; k < 4; k++) {
            float4 a = Ap[k], b = Bp[k];
            float dx = a.x - b.x, dy = a.y - b.y, dz = a.z - b.z, dw = a.w - b.w;
            acc += dx * dx + dy * dy + dz * dz + dw * dw;
        }
        acc += __shfl_xor_sync(0xffffffffu, acc, 1);
        acc += __shfl_xor_sync(0xffffffffu, acc, 2);
        float de = __shfl_sync(0xffffffffu, acc, (lane & 7) * 4);
        float gp = gs * gate[d * NEX + myex];
        float m = gp;
#pragma unroll
        for (int o = 1; o < 8; o <<= 1) m = fmaxf(m, __shfl_xor_sync(0xffffffffu, m, o, 8));
        float wgt = expf(gp - m);
        float sw = wgt;
#pragma unroll
        for (int o = 1; o < 8; o <<= 1) sw += __shfl_xor_sync(0xffffffffu, sw, o, 8);
        float num = de * wgt;
#pragma unroll
        for (int o = 1; o < 8; o <<= 1) num += __shfl_xor_sync(0xffffffffu, num, o, 8);
        if (lane == 0) part += fabsf(num / sw / dis[e] - 1.0f);
    }
    if (lane == 0) warp_part[w] = part;
    __syncthreads();
    if (tid == 0) {
        float s = 0.0f;
#pragma unroll
        for (int k = 0; k < 8; k++) s += warp_part[k];
        atomicAdd(g_loss, s);
    }
}

__global__ void k_final(float* __restrict__ lossp, float invE2) {
    lossp[0] = g_loss[0] * invE2;
}

extern "C" void kernel_launch(void* const* d_in, const int* in_sizes, int n_in,
                              void* d_out, int out_size) {
    const float* x0   = (const float*)d_in[0];
    const float* x1   = (const float*)d_in[1];
    const float* W1   = (const float*)d_in[2];
    const float* b1   = (const float*)d_in[3];
    const float* W2   = (const float*)d_in[4];
    const float* b2   = (const float*)d_in[5];
    const float* Wc   = (const float*)d_in[6];
    const float* bc   = (const float*)d_in[7];
    const float* emb  = (const float*)d_in[8];
    const float* dis  = (const float*)d_in[9];
    const int*   ei0  = (const int*)d_in[10];
    const int*   ei1  = (const int*)d_in[11];
    const int*   bat0 = (const int*)d_in[12];
    const int*   bat1 = (const int*)d_in[13];
    const int*   ei2  = (const int*)d_in[14];

    int N  = in_sizes[0] / 64;
    int E  = in_sizes[10] / 2;
    int B  = in_sizes[8] / (NEX * EMBD);
    int E2 = in_sizes[14] / 2;
    int n2 = 2 * N;

    float* out = (float*)d_out;
    float* lossp = out + (out_size - 1);

    void *p_cnt_i, *p_starts, *p_cursor, *p_dinv, *p_pool, *p_cnt, *p_loss;
    void *p_bins2, *p_starts2, *p_cursor2, *p_h, *p_bsum, *p_bsum2;
    cudaGetSymbolAddress(&p_cnt_i,  g_cnt_i);
    cudaGetSymbolAddress(&p_starts, g_starts);
    cudaGetSymbolAddress(&p_cursor, g_cursor);
    cudaGetSymbolAddress(&p_dinv,   g_dinv);
    cudaGetSymbolAddress(&p_pool,   g_pool);
    cudaGetSymbolAddress(&p_cnt,    g_cnt);
    cudaGetSymbolAddress(&p_loss,   g_loss);
    cudaGetSymbolAddress(&p_h,      g_h);
    cudaGetSymbolAddress(&p_bins2,  g_bins2);
    cudaGetSymbolAddress(&p_starts2, g_starts2);
    cudaGetSymbolAddress(&p_cursor2, g_cursor2);
    cudaGetSymbolAddress(&p_bsum,   g_bsum);
    cudaGetSymbolAddress(&p_bsum2,  g_bsum2);

    // lazily-created side streams + events (host objects, not device memory;
    // graph content is identical on every call)
    static cudaStream_t s1 = 0, s2 = 0, s3 = 0;
    static cudaEvent_t evR = 0, ev1 = 0, ev2 = 0, ev3 = 0, evScan = 0;
    if (!s1) {
        cudaStreamCreateWithFlags(&s1, cudaStreamNonBlocking);
        cudaStreamCreateWithFlags(&s2, cudaStreamNonBlocking);
        cudaStreamCreateWithFlags(&s3, cudaStreamNonBlocking);
        cudaEventCreateWithFlags(&evR, cudaEventDisableTiming);
        cudaEventCreateWithFlags(&ev1, cudaEventDisableTiming);
        cudaEventCreateWithFlags(&ev2, cudaEventDisableTiming);
        cudaEventCreateWithFlags(&ev3, cudaEventDisableTiming);
        cudaEventCreateWithFlags(&evScan, cudaEventDisableTiming);
    }

    const int T = 256;

    // fork point
    cudaEventRecord(evR, 0);

    // ---- branch B (s1): loss-edge bucketing, independent until k_loss ----
    cudaStreamWaitEvent(s1, evR, 0);
    cudaMemsetAsync(p_bins2, 0, (size_t)NB * sizeof(int), s1);
    int G2 = (B + STILE - 1) / STILE;
    k_hist<<<(E2 + T - 1) / T, T, 0, s1>>>(ei2, (int*)p_bins2, E2);
    k_sc1<<<G2, 256, 0, s1>>>((const int*)p_bins2, B, (int*)p_bsum2);
    k_sc2<<<1, 1024, 0, s1>>>(G2, (int*)p_bsum2);
    k_sc3<<<G2, 256, 0, s1>>>((const int*)p_bins2, B, (int*)p_starts2, (int*)p_cursor2,
                              (float*)0, E2, (const int*)p_bsum2);
    k_fill2<<<(E2 + T - 1) / T, T, 0, s1>>>(ei2, E2);
    cudaEventRecord(ev1, s1);

    // ---- branch C (s2): pool/cnt/loss memsets + node counts ----
    cudaStreamWaitEvent(s2, evR, 0);
    cudaMemsetAsync(p_pool, 0, (size_t)NB * 64 * sizeof(float), s2);
    cudaMemsetAsync(p_cnt,  0, (size_t)2 * NB * sizeof(float), s2);
    cudaMemsetAsync(p_loss, 0, sizeof(float), s2);
    k_cnt<<<(n2 + T - 1) / T, T, 0, s2>>>(bat0, bat1, n2);
    cudaEventRecord(ev2, s2);

    // ---- main (stream 0): CSR histogram + scan ----
    cudaMemsetAsync(p_cnt_i, 0, (size_t)n2 * sizeof(int));
    int G = (n2 + STILE - 1) / STILE;
    k_hist2<<<(2 * E + T - 1) / T, T>>>(ei0 + E, ei1 + E, E);
    k_sc1<<<G, 256>>>((const int*)p_cnt_i, n2, (int*)p_bsum);
    k_sc2<<<1, 1024>>>(G, (int*)p_bsum);
    k_sc3<<<G, 256>>>((const int*)p_cnt_i, n2, (int*)p_starts, (int*)p_cursor,
                      (float*)p_dinv, 2 * E, (const int*)p_bsum);
    cudaEventRecord(evScan, 0);

    // ---- branch D (s3): CSR fill, overlaps gemm64 on main ----
    cudaStreamWaitEvent(s3, evScan, 0);
    k_fill<<<(2 * E + T - 1) / T, T, 0, s3>>>(ei0, ei1, E);
    cudaEventRecord(ev3, s3);

    // ---- main: conv1 GEMM (needs only dinv) ----
    k_gemm<64><<<((long)n2 * 4 + T - 1) / T, T>>>(x0, x1, N, W1, n2);
    cudaStreamWaitEvent(0, ev3, 0);     // join CSR fill
    k_gather1<<<((long)n2 * 16 + T - 1) / T, T>>>(b1, n2);
    k_gemm<32><<<((long)n2 * 2 + T - 1) / T, T>>>((const float*)p_h,
                                                  (const float*)p_h + (size_t)N * 64,
                                                  N, W2, n2);
    cudaStreamWaitEvent(0, ev2, 0);     // join pool/cnt memsets + k_cnt
    k_gather2<<<((long)n2 * 8 + T - 1) / T, T>>>(b2, bat0, bat1, n2);

    // gating softmax -> d_out[0 .. B*8)
    k_gate<<<(B + T - 1) / T, T>>>(Wc, bc, out, B);

    // distortion loss (needs bucketing branch)
    cudaStreamWaitEvent(0, ev1, 0);
    k_loss<<<B, 256>>>(emb, out, dis, ei2, E2);
    k_final<<<1, 1>>>(lossp, 1.0f / (float)E2);
}

// round 6
// speedup vs baseline: 1.6900x; 1.0142x over previous
#include <cuda_runtime.h>
#include <math.h>

#define NN   50000
#define N2   (2 * NN)
#define NE_  800000
#define E2X  (2 * NE_)
#define NB   4096
#define NEX  8
#define EMBD 64
#define E2M  131072
#define STILE 4096   // scan tile per block (256 threads * 16)

// ---- device scratch (no allocations allowed) ----
__device__ __align__(16) float g_xw[N2 * 64];   // X@W (conv1: unscaled; conv2: dinv-scaled)
__device__ __align__(16) float g_h[N2 * 64];    // hidden after conv1
__device__ __align__(16) float g_dinv[N2];
__device__ __align__(16) int   g_cnt_i[N2];
__device__ __align__(16) int   g_starts[N2 + 1];
__device__ __align__(16) int   g_cursor[N2];
__device__ __align__(16) int   g_csr[E2X];
__device__ __align__(16) float g_pool[NB * 64];
__device__ __align__(16) float g_cnt[2 * NB];
__device__ __align__(16) int   g_bins2[NB];
__device__ __align__(16) int   g_starts2[NB + 1];
__device__ __align__(16) int   g_cursor2[NB];
__device__ __align__(16) int   g_order[E2M];
__device__ __align__(16) int   g_bsum[1024];
__device__ __align__(16) int   g_bsum2[1024];
__device__ int   g_done[1];
__device__ float g_loss[1];

static __device__ __forceinline__ void red_add_v4(float4* p, float4 v) {
    asm volatile("red.global.add.v4.f32 [%0], {%1, %2, %3, %4};"
                 :: "l"(p), "f"(v.x), "f"(v.y), "f"(v.z), "f"(v.w)
                 : "memory");
}

// ---------------- histogram over BOTH scales' dst ----------------
__global__ void k_hist2(const int* __restrict__ dst0, const int* __restrict__ dst1, int E) {
    int e = blockIdx.x * blockDim.x + threadIdx.x;
    if (e < E)           atomicAdd(&g_cnt_i[dst0[e]], 1);
    else if (e < 2 * E)  atomicAdd(&g_cnt_i[dst1[e - E] + NN], 1);
}

// ---------------- loss-edge histogram ----------------
__global__ void k_hist(const int* __restrict__ key, int* __restrict__ bins, int n) {
    int e = blockIdx.x * blockDim.x + threadIdx.x;
    if (e < n) atomicAdd(&bins[key[e]], 1);
}

// ================= 3-pass multi-block exclusive scan =================
__global__ void k_sc1(const int* __restrict__ cnt, int n, int* __restrict__ bsum) {
    int b = blockIdx.x, t = threadIdx.x;
    long base = (long)b * STILE + (long)t * 16;
    int s = 0;
    if (base + 16 <= n) {
        const int4* p = (const int4*)(cnt + base);
        int4 a = p[0], bb = p[1], c = p[2], d = p[3];
        s = a.x + a.y + a.z + a.w + bb.x + bb.y + bb.z + bb.w
          + c.x + c.y + c.z + c.w + d.x + d.y + d.z + d.w;
    } else {
        for (int k = 0; k < 16; k++) { long i = base + k; if (i < n) s += cnt[i]; }
    }
    __shared__ int sh[256];
    sh[t] = s;
    __syncthreads();
    for (int o = 128; o > 0; o >>= 1) {
        if (t < o) sh[t] += sh[t + o];
        __syncthreads();
    }
    if (t == 0) bsum[b] = sh[0];
}

__global__ void k_sc2(int G, int* __restrict__ bsum) {
    __shared__ int sh[1024];
    int t = threadIdx.x;
    int v = (t < G) ? bsum[t] : 0;
    sh[t] = v;
    __syncthreads();
    for (int o = 1; o < 1024; o <<= 1) {
        int u = (t >= o) ? sh[t - o] : 0;
        __syncthreads();
        sh[t] += u;
        __syncthreads();
    }
    if (t < G) bsum[t] = sh[t] - v;   // exclusive
}

__global__ void k_sc3(const int* __restrict__ cnt, int n,
                      int* __restrict__ starts, int* __restrict__ cursor,
                      float* __restrict__ dinv, int total, const int* __restrict__ bsum) {
    int b = blockIdx.x, t = threadIdx.x;
    long base = (long)b * STILE + (long)t * 16;
    int c[16];
    bool full = (base + 16 <= n);
    if (full) {
        const int4* p = (const int4*)(cnt + base);
        int4 a0 = p[0], a1 = p[1], a2 = p[2], a3 = p[3];
        c[0] = a0.x; c[1] = a0.y; c[2] = a0.z; c[3] = a0.w;
        c[4] = a1.x; c[5] = a1.y; c[6] = a1.z; c[7] = a1.w;
        c[8] = a2.x; c[9] = a2.y; c[10] = a2.z; c[11] = a2.w;
        c[12] = a3.x; c[13] = a3.y; c[14] = a3.z; c[15] = a3.w;
    } else {
        for (int k = 0; k < 16; k++) { long i = base + k; c[k] = (i < n) ? cnt[i] : 0; }
    }
    int pref[16];
    int s = 0;
#pragma unroll
    for (int k = 0; k < 16; k++) { pref[k] = s; s += c[k]; }
    __shared__ int sh[256];
    sh[t] = s;
    __syncthreads();
    for (int o = 1; o < 256; o <<= 1) {
        int u = (t >= o) ? sh[t - o] : 0;
        __syncthreads();
        sh[t] += u;
        __syncthreads();
    }
    int off = bsum[b] + sh[t] - s;
    if (full) {
        int4 o4[4];
#pragma unroll
        for (int j = 0; j < 4; j++) {
            o4[j].x = off + pref[4 * j];     o4[j].y = off + pref[4 * j + 1];
            o4[j].z = off + pref[4 * j + 2]; o4[j].w = off + pref[4 * j + 3];
        }
        int4* ps = (int4*)(starts + base);
        int4* pc = (int4*)(cursor + base);
#pragma unroll
        for (int j = 0; j < 4; j++) { ps[j] = o4[j]; pc[j] = o4[j]; }
        if (dinv) {
            float4* pd = (float4*)(dinv + base);
#pragma unroll
            for (int j = 0; j < 4; j++)
                pd[j] = make_float4(rsqrtf((float)c[4 * j] + 1.0f),
                                    rsqrtf((float)c[4 * j + 1] + 1.0f),
                                    rsqrtf((float)c[4 * j + 2] + 1.0f),
                                    rsqrtf((float)c[4 * j + 3] + 1.0f));
        }
    } else {
        for (int k = 0; k < 16; k++) {
            long i = base + k;
            if (i < n) {
                int v = off + pref[k];
                starts[i] = v; cursor[i] = v;
                if (dinv) dinv[i] = rsqrtf((float)c[k] + 1.0f);
            }
        }
    }
    if (b == 0 && t == 0) starts[n] = total;
}

// ---------------- CSR fill over both scales ----------------
__global__ void k_fill(const int* __restrict__ ei0, const int* __restrict__ ei1, int E) {
    int e = blockIdx.x * blockDim.x + threadIdx.x;
    int s, d;
    if (e < E)          { s = ei0[e];          d = ei0[E + e]; }
    else if (e < 2 * E) { s = ei1[e - E] + NN; d = ei1[E + e - E] + NN; }
    else return;
    int pos = atomicAdd(&g_cursor[d], 1);
    g_csr[pos] = s;
}

// ---------------- loss-edge bucket fill ----------------
__global__ void k_fill2(const int* __restrict__ srow, int E2) {
    int e = blockIdx.x * blockDim.x + threadIdx.x;
    if (e >= E2) return;
    int pos = atomicAdd(&g_cursor2[srow[e]], 1);
    g_order[pos] = e;
}

// ------- GEMM: g_xw = [dinv *] (X @ W).  PARTS threads per row, 16 cols each -------
template <int KOUT, bool SCALE>
__global__ void k_gemm(const float* __restrict__ X0, const float* __restrict__ X1,
                       int splitN, const float* __restrict__ W, int n2) {
    constexpr int PARTS = KOUT / 16;
    __shared__ float Ws[64 * KOUT];
    for (int i = threadIdx.x; i < 64 * KOUT; i += blockDim.x) Ws[i] = W[i];
    __syncthreads();
    int idx = blockIdx.x * blockDim.x + threadIdx.x;
    int row = idx / PARTS;
    int part = idx - row * PARTS;
    if (row >= n2) return;
    const float4* xr = (const float4*)((row < splitN)
                       ? (X0 + (size_t)row * 64)
                       : (X1 + (size_t)(row - splitN) * 64));
    float acc[16];
#pragma unroll
    for (int c = 0; c < 16; c++) acc[c] = 0.0f;
#pragma unroll 4
    for (int kk = 0; kk < 16; kk++) {
        float4 xv = xr[kk];
#pragma unroll
        for (int j = 0; j < 4; j++) {
            float xk = (j == 0) ? xv.x : (j == 1) ? xv.y : (j == 2) ? xv.z : xv.w;
            const float4* wrow = (const float4*)(Ws + (kk * 4 + j) * KOUT + part * 16);
            float4 w0 = wrow[0], w1 = wrow[1], w2 = wrow[2], w3 = wrow[3];
            acc[0]  += xk * w0.x; acc[1]  += xk * w0.y; acc[2]  += xk * w0.z; acc[3]  += xk * w0.w;
            acc[4]  += xk * w1.x; acc[5]  += xk * w1.y; acc[6]  += xk * w1.z; acc[7]  += xk * w1.w;
            acc[8]  += xk * w2.x; acc[9]  += xk * w2.y; acc[10] += xk * w2.z; acc[11] += xk * w2.w;
            acc[12] += xk * w3.x; acc[13] += xk * w3.y; acc[14] += xk * w3.z; acc[15] += xk * w3.w;
        }
    }
    float di = SCALE ? g_dinv[row] : 1.0f;
    float4* y4 = (float4*)(g_xw + (size_t)row * KOUT + part * 16);
#pragma unroll
    for (int j = 0; j < 4; j++)
        y4[j] = make_float4(di * acc[4 * j], di * acc[4 * j + 1],
                            di * acc[4 * j + 2], di * acc[4 * j + 3]);
}

// ------------- gather conv1: h = dinv_d*(sum_in dinv_s*xw_s + dinv_d*xw_d) + b1 (C=64) -------------
__global__ void k_gather1(const float* __restrict__ bias, int n2) {
    int idx = blockIdx.x * blockDim.x + threadIdx.x;
    int i = idx >> 4;
    int q = idx & 15;
    if (i >= n2) return;
    const float4* xs4 = (const float4*)g_xw;
    float di = g_dinv[i];
    float4 sv = xs4[(size_t)i * 16 + q];
    float4 acc = make_float4(di * sv.x, di * sv.y, di * sv.z, di * sv.w);  // self term
    int b0 = g_starts[i], b1 = g_starts[i + 1];
    int j = b0;
    for (; j + 3 < b1; j += 4) {
        int s0 = g_csr[j], s1 = g_csr[j + 1], s2 = g_csr[j + 2], s3 = g_csr[j + 3];
        float d0 = g_dinv[s0], d1 = g_dinv[s1], d2 = g_dinv[s2], d3 = g_dinv[s3];
        float4 v0 = xs4[(size_t)s0 * 16 + q];
        float4 v1 = xs4[(size_t)s1 * 16 + q];
        float4 v2 = xs4[(size_t)s2 * 16 + q];
        float4 v3 = xs4[(size_t)s3 * 16 + q];
        acc.x += d0 * v0.x + d1 * v1.x + d2 * v2.x + d3 * v3.x;
        acc.y += d0 * v0.y + d1 * v1.y + d2 * v2.y + d3 * v3.y;
        acc.z += d0 * v0.z + d1 * v1.z + d2 * v2.z + d3 * v3.z;
        acc.w += d0 * v0.w + d1 * v1.w + d2 * v2.w + d3 * v3.w;
    }
    for (; j < b1; j++) {
        int s = g_csr[j];
        float ds = g_dinv[s];
        float4 v = xs4[(size_t)s * 16 + q];
        acc.x += ds * v.x; acc.y += ds * v.y; acc.z += ds * v.z; acc.w += ds * v.w;
    }
    float4 bq = ((const float4*)bias)[q];
    ((float4*)g_h)[(size_t)i * 16 + q] =
        make_float4(di * acc.x + bq.x, di * acc.y + bq.y,
                    di * acc.z + bq.z, di * acc.w + bq.w);
}

// ------------- gather conv2 (xs pre-scaled) + fused mean-pool accumulate (C=32) -------------
__global__ void k_gather2(const float* __restrict__ bias, const int* __restrict__ bat0,
                          const int* __restrict__ bat1, int n2) {
    int idx = blockIdx.x * blockDim.x + threadIdx.x;
    int i = idx >> 3;
    int q = idx & 7;
    if (i >= n2) return;
    const float4* xs4 = (const float4*)g_xw;
    float4 acc = xs4[(size_t)i * 8 + q];
    int b0 = g_starts[i], b1 = g_starts[i + 1];
    int j = b0;
    for (; j + 3 < b1; j += 4) {
        int s0 = g_csr[j], s1 = g_csr[j + 1], s2 = g_csr[j + 2], s3 = g_csr[j + 3];
        float4 v0 = xs4[(size_t)s0 * 8 + q];
        float4 v1 = xs4[(size_t)s1 * 8 + q];
        float4 v2 = xs4[(size_t)s2 * 8 + q];
        float4 v3 = xs4[(size_t)s3 * 8 + q];
        acc.x += (v0.x + v1.x) + (v2.x + v3.x);
        acc.y += (v0.y + v1.y) + (v2.y + v3.y);
        acc.z += (v0.z + v1.z) + (v2.z + v3.z);
        acc.w += (v0.w + v1.w) + (v2.w + v3.w);
    }
    for (; j < b1; j++) {
        float4 v = xs4[(size_t)g_csr[j] * 8 + q];
        acc.x += v.x; acc.y += v.y; acc.z += v.z; acc.w += v.w;
    }
    float di = g_dinv[i];
    float4 bq = ((const float4*)bias)[q];
    float4 h2 = make_float4(di * acc.x + bq.x, di * acc.y + bq.y,
                            di * acc.z + bq.z, di * acc.w + bq.w);
    int scale = (i < NN) ? 0 : 1;
    int b = (i < NN) ? bat0[i] : bat1[i - NN];
    red_add_v4(((float4*)g_pool) + b * 16 + scale * 8 + q, h2);
}

// ---------------- per-graph node count, both scales ----------------
__global__ void k_cnt(const int* __restrict__ bat0, const int* __restrict__ bat1, int n2) {
    int i = blockIdx.x * blockDim.x + threadIdx.x;
    if (i >= n2) return;
    if (i < NN) atomicAdd(&g_cnt[bat0[i]], 1.0f);
    else        atomicAdd(&g_cnt[NB + bat1[i - NN]], 1.0f);
}

// ---------------- gate = softmax(concat(x0,x1) @ Wc + bc) ----------------
__global__ void k_gate(const float* __restrict__ Wc, const float* __restrict__ bc,
                       float* __restrict__ out, int B) {
    int b = blockIdx.x * blockDim.x + threadIdx.x;
    if (b >= B) return;
    float inv0 = 1.0f / fmaxf(g_cnt[b], 1.0f);
    float inv1 = 1.0f / fmaxf(g_cnt[NB + b], 1.0f);
    float logit[NEX];
#pragma unroll
    for (int e = 0; e < NEX; e++) logit[e] = bc[e];
    const float* pr = g_pool + b * 64;
    for (int k = 0; k < 64; k++) {
        float xv = pr[k] * (k < 32 ? inv0 : inv1);
#pragma unroll
        for (int e = 0; e < NEX; e++) logit[e] += xv * Wc[k * NEX + e];
    }
    float m = logit[0];
#pragma unroll
    for (int e = 1; e < NEX; e++) m = fmaxf(m, logit[e]);
    float ssum = 0.0f;
#pragma unroll
    for (int e = 0; e < NEX; e++) { logit[e] = expf(logit[e] - m); ssum += logit[e]; }
    float is = 1.0f / ssum;
#pragma unroll
    for (int e = 0; e < NEX; e++) out[b * NEX + e] = logit[e] * is;
}

// ---------- distortion loss, bucketed by source graph; finalize fused (last block) ----------
__global__ void k_loss(const float* __restrict__ emb, const float* __restrict__ gate,
                       const float* __restrict__ dis, const int* __restrict__ ei2, int E2,
                       float* __restrict__ lossp, float invE2) {
    __shared__ float sa[NEX * EMBD];       // emb[g] row (512 floats)
    __shared__ float warp_part[8];
    int g = blockIdx.x;
    int tid = threadIdx.x;
    for (int i = tid; i < NEX * EMBD; i += blockDim.x)
        sa[i] = emb[(long)g * (NEX * EMBD) + i];
    __syncthreads();

    int lane = tid & 31;
    int w = tid >> 5;
    int myex = lane & 7;
    int ex = lane >> 2;
    int ch = lane & 3;
    float gs = gate[g * NEX + myex];
    const float4* Ap = ((const float4*)sa) + ex * 16 + ch * 4;

    float part = 0.0f;
    int b0 = g_starts2[g], b1 = g_starts2[g + 1];
    for (int j = b0 + w; j < b1; j += 8) {
        int e = g_order[j];
        int d = ei2[E2 + e];
        const float4* Bp = (const float4*)(emb + (long)d * (NEX * EMBD)) + ex * 16 + ch * 4;
        float acc = 0.0f;
#pragma unroll
        for (int k = 0; k < 4; k++) {
            float4 a = Ap[k], b = Bp[k];
            float dx = a.x - b.x, dy = a.y - b.y, dz = a.z - b.z, dw = a.w - b.w;
            acc += dx * dx + dy * dy + dz * dz + dw * dw;
        }
        acc += __shfl_xor_sync(0xffffffffu, acc, 1);
        acc += __shfl_xor_sync(0xffffffffu, acc, 2);
        float de = __shfl_sync(0xffffffffu, acc, (lane & 7) * 4);
        float gp = gs * gate[d * NEX + myex];
        float m = gp;
#pragma unroll
        for (int o = 1; o < 8; o <<= 1) m = fmaxf(m, __shfl_xor_sync(0xffffffffu, m, o, 8));
        float wgt = expf(gp - m);
        float sw = wgt;
#pragma unroll
        for (int o = 1; o < 8; o <<= 1) sw += __shfl_xor_sync(0xffffffffu, sw, o, 8);
        float num = de * wgt;
#pragma unroll
        for (int o = 1; o < 8; o <<= 1) num += __shfl_xor_sync(0xffffffffu, num, o, 8);
        if (lane == 0) part += fabsf(num / sw / dis[e] - 1.0f);
    }
    if (lane == 0) warp_part[w] = part;
    __syncthreads();
    if (tid == 0) {
        float s = 0.0f;
#pragma unroll
        for (int k = 0; k < 8; k++) s += warp_part[k];
        atomicAdd(g_loss, s);
        __threadfence();
        int ticket = atomicAdd(g_done, 1);
        if (ticket == gridDim.x - 1) {
            float total = atomicAdd(g_loss, 0.0f);   // L2-coherent read
            lossp[0] = total * invE2;
        }
    }
}

extern "C" void kernel_launch(void* const* d_in, const int* in_sizes, int n_in,
                              void* d_out, int out_size) {
    const float* x0   = (const float*)d_in[0];
    const float* x1   = (const float*)d_in[1];
    const float* W1   = (const float*)d_in[2];
    const float* b1   = (const float*)d_in[3];
    const float* W2   = (const float*)d_in[4];
    const float* b2   = (const float*)d_in[5];
    const float* Wc   = (const float*)d_in[6];
    const float* bc   = (const float*)d_in[7];
    const float* emb  = (const float*)d_in[8];
    const float* dis  = (const float*)d_in[9];
    const int*   ei0  = (const int*)d_in[10];
    const int*   ei1  = (const int*)d_in[11];
    const int*   bat0 = (const int*)d_in[12];
    const int*   bat1 = (const int*)d_in[13];
    const int*   ei2  = (const int*)d_in[14];

    int N  = in_sizes[0] / 64;
    int E  = in_sizes[10] / 2;
    int B  = in_sizes[8] / (NEX * EMBD);
    int E2 = in_sizes[14] / 2;
    int n2 = 2 * N;

    float* out = (float*)d_out;
    float* lossp = out + (out_size - 1);

    void *p_cnt_i, *p_starts, *p_cursor, *p_dinv, *p_pool, *p_cnt, *p_loss;
    void *p_bins2, *p_starts2, *p_cursor2, *p_h, *p_bsum, *p_bsum2, *p_done;
    cudaGetSymbolAddress(&p_cnt_i,  g_cnt_i);
    cudaGetSymbolAddress(&p_starts, g_starts);
    cudaGetSymbolAddress(&p_cursor, g_cursor);
    cudaGetSymbolAddress(&p_dinv,   g_dinv);
    cudaGetSymbolAddress(&p_pool,   g_pool);
    cudaGetSymbolAddress(&p_cnt,    g_cnt);
    cudaGetSymbolAddress(&p_loss,   g_loss);
    cudaGetSymbolAddress(&p_h,      g_h);
    cudaGetSymbolAddress(&p_bins2,  g_bins2);
    cudaGetSymbolAddress(&p_starts2, g_starts2);
    cudaGetSymbolAddress(&p_cursor2, g_cursor2);
    cudaGetSymbolAddress(&p_bsum,   g_bsum);
    cudaGetSymbolAddress(&p_bsum2,  g_bsum2);
    cudaGetSymbolAddress(&p_done,   g_done);

    static cudaStream_t s1 = 0, s2 = 0, s3 = 0;
    static cudaEvent_t evR = 0, ev1 = 0, ev2 = 0, ev3 = 0;
    if (!s1) {
        cudaStreamCreateWithFlags(&s1, cudaStreamNonBlocking);
        cudaStreamCreateWithFlags(&s2, cudaStreamNonBlocking);
        cudaStreamCreateWithFlags(&s3, cudaStreamNonBlocking);
        cudaEventCreateWithFlags(&evR, cudaEventDisableTiming);
        cudaEventCreateWithFlags(&ev1, cudaEventDisableTiming);
        cudaEventCreateWithFlags(&ev2, cudaEventDisableTiming);
        cudaEventCreateWithFlags(&ev3, cudaEventDisableTiming);
    }

    const int T = 256;

    // fork point
    cudaEventRecord(evR, 0);

    // ---- branch B (s1): loss-edge bucketing, independent until k_loss ----
    cudaStreamWaitEvent(s1, evR, 0);
    cudaMemsetAsync(p_bins2, 0, (size_t)NB * sizeof(int), s1);
    int G2 = (B + STILE - 1) / STILE;
    k_hist<<<(E2 + T - 1) / T, T, 0, s1>>>(ei2, (int*)p_bins2, E2);
    k_sc1<<<G2, 256, 0, s1>>>((const int*)p_bins2, B, (int*)p_bsum2);
    k_sc2<<<1, 1024, 0, s1>>>(G2, (int*)p_bsum2);
    k_sc3<<<G2, 256, 0, s1>>>((const int*)p_bins2, B, (int*)p_starts2, (int*)p_cursor2,
                              (float*)0, E2, (const int*)p_bsum2);
    k_fill2<<<(E2 + T - 1) / T, T, 0, s1>>>(ei2, E2);
    cudaEventRecord(ev1, s1);

    // ---- branch C (s2): pool/cnt/loss/done memsets + node counts ----
    cudaStreamWaitEvent(s2, evR, 0);
    cudaMemsetAsync(p_pool, 0, (size_t)NB * 64 * sizeof(float), s2);
    cudaMemsetAsync(p_cnt,  0, (size_t)2 * NB * sizeof(float), s2);
    cudaMemsetAsync(p_loss, 0, sizeof(float), s2);
    cudaMemsetAsync(p_done, 0, sizeof(int), s2);
    k_cnt<<<(n2 + T - 1) / T, T, 0, s2>>>(bat0, bat1, n2);
    cudaEventRecord(ev2, s2);

    // ---- branch D (s3): conv1 GEMM, fully independent of CSR build (no dinv) ----
    cudaStreamWaitEvent(s3, evR, 0);
    k_gemm<64, false><<<((long)n2 * 4 + T - 1) / T, T, 0, s3>>>(x0, x1, N, W1, n2);
    cudaEventRecord(ev3, s3);

    // ---- main (stream 0): CSR histogram + scan + fill ----
    cudaMemsetAsync(p_cnt_i, 0, (size_t)n2 * sizeof(int));
    int G = (n2 + STILE - 1) / STILE;
    k_hist2<<<(2 * E + T - 1) / T, T>>>(ei0 + E, ei1 + E, E);
    k_sc1<<<G, 256>>>((const int*)p_cnt_i, n2, (int*)p_bsum);
    k_sc2<<<1, 1024>>>(G, (int*)p_bsum);
    k_sc3<<<G, 256>>>((const int*)p_cnt_i, n2, (int*)p_starts, (int*)p_cursor,
                      (float*)p_dinv, 2 * E, (const int*)p_bsum);
    k_fill<<<(2 * E + T - 1) / T, T>>>(ei0, ei1, E);

    // ---- main: conv1 gather (join gemm64), conv2 gemm + gather ----
    cudaStreamWaitEvent(0, ev3, 0);     // join gemm64
    k_gather1<<<((long)n2 * 16 + T - 1) / T, T>>>(b1, n2);
    k_gemm<32, true><<<((long)n2 * 2 + T - 1) / T, T>>>((const float*)p_h,
                                                        (const float*)p_h + (size_t)N * 64,
                                                        N, W2, n2);
    cudaStreamWaitEvent(0, ev2, 0);     // join pool/cnt memsets + k_cnt
    k_gather2<<<((long)n2 * 8 + T - 1) / T, T>>>(b2, bat0, bat1, n2);

    // gating softmax -> d_out[0 .. B*8)
    k_gate<<<(B + T - 1) / T, T>>>(Wc, bc, out, B);

    // distortion loss (needs bucketing branch); finalize fused into last block
    cudaStreamWaitEvent(0, ev1, 0);
    k_loss<<<B, 256>>>(emb, out, dis, ei2, E2, lossp, 1.0f / (float)E2);
}